// round 17
// baseline (speedup 1.0000x reference)
#include <cuda_runtime.h>
#include <cuda_bf16.h>
#include <math.h>

#define BB 64       // batch
#define TT 32       // seq len
#define EE 512      // embed
#define HH 512      // hidden
#define GG 2048     // 4*H
#define VV 10000    // vocab
#define MM 2048     // rows = TT*BB

#define NLSTM 128               // lstm CTAs per fused launch
#define NLOG  157               // logits tile CTAs per fused launch (157*64 >= VV)

// ---------------- scratch (device globals; no allocation allowed) -------------
__device__ __align__(16) float g_xg[MM * GG];         // [m][g]  16 MB
__device__ __align__(16) float g_hall[MM * HH];       // [m][j]   4 MB
__device__ __align__(16) float g_h[2][HH * BB];       // double-buffered h, [j][b]
__device__ __align__(16) float g_c[HH * BB];          // cell state [j][b]
__device__ int g_is64;

// ---------------- helpers ----------------------------------------------------
__global__ void init_state() {
    int i = blockIdx.x * blockDim.x + threadIdx.x;
    if (i < HH * BB) { g_h[0][i] = 0.f; g_c[i] = 0.f; }
}

// Detect whether captions buffer is int64 or int32 on device.
__global__ void detect_cap(const int* cap) {
    int nz = 0;
    for (int i = 1 + 2 * threadIdx.x; i < 2 * BB * TT; i += 2 * blockDim.x)
        nz |= (cap[i] != 0);
    nz = __syncthreads_or(nz);
    if (threadIdx.x == 0) g_is64 = (nz == 0);
}

__device__ __forceinline__ void cp16(void* smem, const void* gmem) {
    unsigned s = (unsigned)__cvta_generic_to_shared(smem);
    asm volatile("cp.async.ca.shared.global [%0], [%1], 16;" :: "r"(s), "l"(gmem));
}
__device__ __forceinline__ void cp_commit() { asm volatile("cp.async.commit_group;"); }
template <int N>
__device__ __forceinline__ void cp_wait() { asm volatile("cp.async.wait_group %0;" :: "n"(N)); }

// ---------------- GEMM 1: x_gates (fp32, PROVEN R5/R15 code) ------------------
__global__ void __launch_bounds__(256) gemm_xg(
    const float* __restrict__ features,
    const void*  __restrict__ captions,
    const float* __restrict__ emb,
    const float* __restrict__ W_ih,
    const float* __restrict__ b_ih,
    const float* __restrict__ b_hh)
{
    __shared__ __align__(16) float As[16][68];
    __shared__ __align__(16) float Bs[16][68];

    const int m0 = blockIdx.y * 64;
    const int n0 = blockIdx.x * 64;
    const int tid = threadIdx.x;
    const int tx = tid & 15, ty = tid >> 4;
    const int lrow = tid >> 2;
    const int lkq  = tid & 3;

    const int m = m0 + lrow;
    const int t = m >> 6, b = m & 63;
    const float* arow;
    if (t == 0) {
        arow = features + (size_t)b * EE;
    } else {
        long long idx;
        if (g_is64) idx = ((const long long*)captions)[b * TT + (t - 1)];
        else        idx = ((const int*)captions)[b * TT + (t - 1)];
        arow = emb + (size_t)idx * EE;
    }
    const float* brow = W_ih + (size_t)(n0 + lrow) * EE;

    float acc[4][4] = {};

    for (int k0 = 0; k0 < EE; k0 += 16) {
        float4 av = *(const float4*)(arow + k0 + lkq * 4);
        float4 bv = *(const float4*)(brow + k0 + lkq * 4);
        __syncthreads();
        As[lkq * 4 + 0][lrow] = av.x; As[lkq * 4 + 1][lrow] = av.y;
        As[lkq * 4 + 2][lrow] = av.z; As[lkq * 4 + 3][lrow] = av.w;
        Bs[lkq * 4 + 0][lrow] = bv.x; Bs[lkq * 4 + 1][lrow] = bv.y;
        Bs[lkq * 4 + 2][lrow] = bv.z; Bs[lkq * 4 + 3][lrow] = bv.w;
        __syncthreads();
        #pragma unroll
        for (int kk = 0; kk < 16; kk++) {
            float4 a4 = *(const float4*)&As[kk][ty * 4];
            float4 b4 = *(const float4*)&Bs[kk][tx * 4];
            acc[0][0] += a4.x * b4.x; acc[0][1] += a4.x * b4.y; acc[0][2] += a4.x * b4.z; acc[0][3] += a4.x * b4.w;
            acc[1][0] += a4.y * b4.x; acc[1][1] += a4.y * b4.y; acc[1][2] += a4.y * b4.z; acc[1][3] += a4.y * b4.w;
            acc[2][0] += a4.z * b4.x; acc[2][1] += a4.z * b4.y; acc[2][2] += a4.z * b4.z; acc[2][3] += a4.z * b4.w;
            acc[3][0] += a4.w * b4.x; acc[3][1] += a4.w * b4.y; acc[3][2] += a4.w * b4.z; acc[3][3] += a4.w * b4.w;
        }
    }

    #pragma unroll
    for (int i = 0; i < 4; i++) {
        int mm = m0 + ty * 4 + i;
        #pragma unroll
        for (int j = 0; j < 4; j++) {
            int nn = n0 + tx * 4 + j;
            g_xg[(size_t)mm * GG + nn] = acc[i][j] + b_ih[nn] + b_hh[nn];
        }
    }
}

// ---------------- Fused step: lstm(t) [CTAs 0..127] + logits(t-1) [128..284] --
// Per-launch lag-1 overlap: the LSTM chain (latency-bound, fma 14%) runs
// concurrently with the fma-bound logits tiles of the PREVIOUS step (h rows
// written by the previous launch -> kernel-boundary sync, race-free).
// Shared-memory union: lstm uses 45.8KB, logits path 8.5KB of the same buffer.
__global__ void __launch_bounds__(256) fused_step(
    int t,
    const float* __restrict__ W_hh,
    const float* __restrict__ W_fc,
    const float* __restrict__ b_fc,
    float* __restrict__ out)
{
    __shared__ __align__(16) float sm[11456];   // 45,824 B

    const int tid = threadIdx.x;

    if (blockIdx.x < NLSTM) {
        // ================= LSTM branch (PROVEN R14 body, smem re-based) ======
        if (t >= TT) return;
        float* hs0 = sm;                 // [2][64*64]
        float* wsb = sm + 8192;          // [2][16*68]
        float* gsh = sm + 8192 + 2176;   // [16*68]

        const int jbase = blockIdx.x * 4;
        const int lc = tid >> 4;
        const int lb = tid & 15;
        const int lcol = (lc >> 2) * HH + jbase + (lc & 3);
        const float* __restrict__ wsrc = W_hh + (size_t)lcol * HH;

        const int b  = tid & 63;
        const int tg = tid >> 6;

        const float* __restrict__ hin  = g_h[t & 1];
        float* __restrict__ hout = g_h[(t + 1) & 1];
        const float* __restrict__ xgt  = g_xg + (size_t)t * BB * GG;

        float4 ainit = *(const float4*)&xgt[(size_t)b * GG + tg * HH + jbase];
        float acc0 = ainit.x, acc1 = ainit.y, acc2 = ainit.z, acc3 = ainit.w;

        #pragma unroll
        for (int r = 0; r < 4; r++) {
            int f = tid + r * 256;
            int k = f >> 4, bq = f & 15;
            cp16(&hs0[k * 64 + bq * 4], &hin[(size_t)k * BB + bq * 4]);
        }
        cp16(&wsb[lc * 68 + lb * 4], wsrc + lb * 4);
        cp_commit();

        #pragma unroll
        for (int kc = 0; kc < 8; kc++) {
            if (kc < 7) {
                float* hsn = sm + ((kc + 1) & 1) * 4096;
                float* wsn = sm + 8192 + ((kc + 1) & 1) * 1088;
                #pragma unroll
                for (int r = 0; r < 4; r++) {
                    int f = tid + r * 256;
                    int k = f >> 4, bq = f & 15;
                    cp16(&hsn[k * 64 + bq * 4],
                         &hin[(size_t)((kc + 1) * 64 + k) * BB + bq * 4]);
                }
                cp16(&wsn[lc * 68 + lb * 4], wsrc + (kc + 1) * 64 + lb * 4);
                cp_commit();
                cp_wait<1>();
            } else {
                cp_wait<0>();
            }
            __syncthreads();

            const float* hc  = sm + (kc & 1) * 4096;
            const float* wsc = sm + 8192 + (kc & 1) * 1088;
            const float* w0p = &wsc[(tg * 4 + 0) * 68];
            const float* w1p = &wsc[(tg * 4 + 1) * 68];
            const float* w2p = &wsc[(tg * 4 + 2) * 68];
            const float* w3p = &wsc[(tg * 4 + 3) * 68];
            #pragma unroll
            for (int k4 = 0; k4 < 16; k4++) {
                float4 w0 = *(const float4*)&w0p[k4 * 4];
                float4 w1 = *(const float4*)&w1p[k4 * 4];
                float4 w2 = *(const float4*)&w2p[k4 * 4];
                float4 w3 = *(const float4*)&w3p[k4 * 4];
                {
                    float h0 = hc[(k4 * 4 + 0) * 64 + b];
                    acc0 += h0 * w0.x; acc1 += h0 * w1.x; acc2 += h0 * w2.x; acc3 += h0 * w3.x;
                }
                {
                    float h1 = hc[(k4 * 4 + 1) * 64 + b];
                    acc0 += h1 * w0.y; acc1 += h1 * w1.y; acc2 += h1 * w2.y; acc3 += h1 * w3.y;
                }
                {
                    float h2 = hc[(k4 * 4 + 2) * 64 + b];
                    acc0 += h2 * w0.z; acc1 += h2 * w1.z; acc2 += h2 * w2.z; acc3 += h2 * w3.z;
                }
                {
                    float h3 = hc[(k4 * 4 + 3) * 64 + b];
                    acc0 += h3 * w0.w; acc1 += h3 * w1.w; acc2 += h3 * w2.w; acc3 += h3 * w3.w;
                }
            }
            __syncthreads();
        }

        gsh[(tg * 4 + 0) * 68 + b] = acc0;
        gsh[(tg * 4 + 1) * 68 + b] = acc1;
        gsh[(tg * 4 + 2) * 68 + b] = acc2;
        gsh[(tg * 4 + 3) * 68 + b] = acc3;
        __syncthreads();

        const int bnl = tid & 63, jl = tid >> 6;
        const float iv = gsh[(0  + jl) * 68 + bnl];
        const float fv = gsh[(4  + jl) * 68 + bnl];
        const float gv = gsh[(8  + jl) * 68 + bnl];
        const float ov = gsh[(12 + jl) * 68 + bnl];
        const int j = jbase + jl;

        float c_old = g_c[(size_t)j * BB + bnl];
        float si = 1.f / (1.f + expf(-iv));
        float sf = 1.f / (1.f + expf(-fv));
        float so = 1.f / (1.f + expf(-ov));
        float tg_ = tanhf(gv);
        float cn = sf * c_old + si * tg_;
        float hn = so * tanhf(cn);
        g_c[(size_t)j * BB + bnl] = cn;
        hout[(size_t)j * BB + bnl] = hn;
        g_hall[((size_t)t * BB + bnl) * HH + j] = hn;

    } else {
        // ================= logits branch (PROVEN xg-style 64x64 tile) ========
        const int tlog = t - 1;              // timestep whose h is complete
        if (tlog < 0) return;

        float (*As)[68] = (float(*)[68])sm;          // 16x68
        float (*Bs)[68] = (float(*)[68])(sm + 1088); // 16x68

        const int n0 = (blockIdx.x - NLSTM) * 64;
        const int m0 = tlog * 64;
        const int tx = tid & 15, ty = tid >> 4;
        const int lrow = tid >> 2;
        const int lkq  = tid & 3;

        const float* arow = g_hall + (size_t)(m0 + lrow) * HH;
        int nb = n0 + lrow; if (nb >= VV) nb = VV - 1;
        const float* brow = W_fc + (size_t)nb * HH;

        float acc[4][4] = {};

        for (int k0 = 0; k0 < HH; k0 += 16) {
            float4 av = *(const float4*)(arow + k0 + lkq * 4);
            float4 bv = *(const float4*)(brow + k0 + lkq * 4);
            __syncthreads();
            As[lkq * 4 + 0][lrow] = av.x; As[lkq * 4 + 1][lrow] = av.y;
            As[lkq * 4 + 2][lrow] = av.z; As[lkq * 4 + 3][lrow] = av.w;
            Bs[lkq * 4 + 0][lrow] = bv.x; Bs[lkq * 4 + 1][lrow] = bv.y;
            Bs[lkq * 4 + 2][lrow] = bv.z; Bs[lkq * 4 + 3][lrow] = bv.w;
            __syncthreads();
            #pragma unroll
            for (int kk = 0; kk < 16; kk++) {
                float4 a4 = *(const float4*)&As[kk][ty * 4];
                float4 b4 = *(const float4*)&Bs[kk][tx * 4];
                acc[0][0] += a4.x * b4.x; acc[0][1] += a4.x * b4.y; acc[0][2] += a4.x * b4.z; acc[0][3] += a4.x * b4.w;
                acc[1][0] += a4.y * b4.x; acc[1][1] += a4.y * b4.y; acc[1][2] += a4.y * b4.z; acc[1][3] += a4.y * b4.w;
                acc[2][0] += a4.z * b4.x; acc[2][1] += a4.z * b4.y; acc[2][2] += a4.z * b4.z; acc[2][3] += a4.z * b4.w;
                acc[3][0] += a4.w * b4.x; acc[3][1] += a4.w * b4.y; acc[3][2] += a4.w * b4.z; acc[3][3] += a4.w * b4.w;
            }
        }

        #pragma unroll
        for (int i = 0; i < 4; i++) {
            int bb = ty * 4 + i;                         // batch (m = tlog*64+bb)
            size_t obase = ((size_t)bb * TT + tlog) * VV;
            #pragma unroll
            for (int j = 0; j < 4; j++) {
                int nn = n0 + tx * 4 + j;
                if (nn < VV) out[obase + nn] = acc[i][j] + b_fc[nn];
            }
        }
    }
}

// ---------------- launch ------------------------------------------------------
extern "C" void kernel_launch(void* const* d_in, const int* in_sizes, int n_in,
                              void* d_out, int out_size)
{
    const float* features = (const float*)d_in[0];
    const void*  captions = d_in[1];
    const float* emb      = (const float*)d_in[2];
    const float* W_ih     = (const float*)d_in[3];
    const float* W_hh     = (const float*)d_in[4];
    const float* b_ih     = (const float*)d_in[5];
    const float* b_hh     = (const float*)d_in[6];
    const float* W_fc     = (const float*)d_in[7];
    const float* b_fc     = (const float*)d_in[8];
    float* out = (float*)d_out;

    init_state<<<(HH * BB + 255) / 256, 256>>>();
    detect_cap<<<1, 256>>>((const int*)captions);

    gemm_xg<<<dim3(GG / 64, MM / 64), 256>>>(features, captions, emb, W_ih, b_ih, b_hh);

    // t = 0..31: lstm(t) + logits(t-1);  t = 32: logits(31) only
    for (int t = 0; t <= TT; t++)
        fused_step<<<NLSTM + NLOG, 256>>>(t, W_hh, W_fc, b_fc, out);
}